// round 5
// baseline (speedup 1.0000x reference)
#include <cuda_runtime.h>
#include <cuda_bf16.h>
#include <cstdint>

typedef unsigned long long ull;

#define B_    64
#define T_    2048
#define H_    512
#define G_    2048      // 4*H
#define NCTA  128       // persistent CTAs, each owns 4 h-cols = 16 gate cols
#define CPC   16        // gate cols per CTA

// ---------------- device scratch (static, allowed) ----------------
__device__ __align__(16) float  g_xg[(size_t)T_ * G_ * B_];      // 1 GiB  [t][pcol][b]
__device__ __align__(16) float  g_hs[(size_t)T_ * H_ * B_];      // 256 MB [t][k][b] natural
__device__ __align__(16) float  g_wh4[NCTA * H_ * CPC];          // 4 MB, permuted W_h [cta][k][16]
__device__ __align__(16) float  g_bossT[G_ * 64];                // [pcol][vocab(pad64)]
__device__ __align__(16) float  g_heroT[G_ * 200];               // [pcol][vocab200]
__device__ __align__(16) float4 g_cwb[G_];                       // (Wc0,Wc1,Wc2,bias) permuted
__device__ __align__(16) float  g_hbuf[2][H_ * B_];              // double-buffered h [k][permuted b]
__device__ unsigned g_barS[8];                                   // per-slice step counters

// ---------------- helpers ----------------
__device__ __forceinline__ ull pk2(float x, float y) {
    ull r; asm("mov.b64 %0, {%1,%2};" : "=l"(r) : "f"(x), "f"(y)); return r;
}
__device__ __forceinline__ float2 upk(ull v) {
    float2 f; asm("mov.b64 {%0,%1}, %2;" : "=f"(f.x), "=f"(f.y) : "l"(v)); return f;
}
__device__ __forceinline__ void fma2(ull& d, ull a, ull b) {
    asm("fma.rn.f32x2 %0, %1, %2, %3;" : "=l"(d) : "l"(a), "l"(b), "l"(d));
}
__device__ __forceinline__ void add2(ull& d, ull a) {
    asm("add.rn.f32x2 %0, %1, %2;" : "=l"(d) : "l"(d), "l"(a));
}
__device__ __forceinline__ void cp16(uint32_t s, const void* g) {
    asm volatile("cp.async.cg.shared.global [%0], [%1], 16;" :: "r"(s), "l"(g) : "memory");
}
__device__ __forceinline__ void cpcommit() { asm volatile("cp.async.commit_group;" ::: "memory"); }
template <int N> __device__ __forceinline__ void cpwait() {
    asm volatile("cp.async.wait_group %0;" :: "n"(N) : "memory");
}
__device__ __forceinline__ float sigf(float x) { return 1.0f / (1.0f + __expf(-x)); }
__device__ __forceinline__ float tanha(float x) {
    float r; asm("tanh.approx.f32 %0, %1;" : "=f"(r) : "f"(x)); return r;
}

// b-permutation for h rows (bank-conflict-free GEMM loads)
__device__ __forceinline__ int permb(int b) {
    int q = b >> 2;
    return (((q & 1) * 8) + (q >> 1)) * 4 + (b & 3);
}

// pcol = cta*16 + gate*4 + j  <->  orig gate col = gate*512 + cta*4 + j
__device__ __forceinline__ int orig_col(int pcol) {
    int cta = pcol >> 4, r = pcol & 15, gate = r >> 2, j = r & 3;
    return gate * H_ + cta * 4 + j;
}

// ---------------- kernel 0: init ----------------
__global__ void k_init() {
    int tid = threadIdx.x + blockIdx.x * blockDim.x;
    if (tid < 8) g_barS[tid] = 0u;
    for (int i = tid; i < H_ * B_; i += blockDim.x * gridDim.x) {
        g_hbuf[0][i] = 0.f;
        g_hbuf[1][i] = 0.f;
    }
}

// ---------------- kernel 1: projections + weight permute ----------------
__global__ void k_prep(const float* __restrict__ boss_table,
                       const float* __restrict__ hero_table,
                       const float* __restrict__ W_i,
                       const float* __restrict__ W_h,
                       const float* __restrict__ b_lstm) {
    int pcol = blockIdx.x;
    int o = orig_col(pcol);
    int tid = threadIdx.x;

    if (tid < 50) {
        float s = 0.f;
        #pragma unroll
        for (int e = 0; e < 32; ++e) s += boss_table[tid * 32 + e] * W_i[e * G_ + o];
        g_bossT[pcol * 64 + tid] = s;
    } else if (tid < 250) {
        int v = tid - 50;
        float s = 0.f;
        #pragma unroll
        for (int e = 0; e < 32; ++e) s += hero_table[v * 32 + e] * W_i[(32 + e) * G_ + o];
        g_heroT[pcol * 200 + v] = s;
    } else if (tid == 250) {
        g_cwb[pcol] = make_float4(W_i[64 * G_ + o], W_i[65 * G_ + o], W_i[66 * G_ + o], b_lstm[o]);
    }
    int cta = pcol >> 4, r = pcol & 15;
    for (int k = tid; k < H_; k += 256) {
        g_wh4[(cta * H_ + k) * CPC + r] = W_h[k * G_ + o];
    }
}

// ---------------- kernel 2: build xg[t][pcol][b] ----------------
__global__ void k_xg(const int* __restrict__ boss_anim,
                     const int* __restrict__ hero_anim,
                     const float* __restrict__ cont) {
    __shared__ int   sb[B_], sh[B_];
    __shared__ float sc[B_][3];
    int t = blockIdx.x, tid = threadIdx.x;
    if (tid < B_) {
        int b = tid;
        int bi = boss_anim[b * T_ + t]; bi = min(max(bi, 0), 49);
        int hi = hero_anim[b * T_ + t]; hi = min(max(hi, 0), 199);
        sb[b] = bi; sh[b] = hi;
        size_t cb = ((size_t)b * T_ + t) * 3;
        sc[b][0] = cont[cb + 0]; sc[b][1] = cont[cb + 1]; sc[b][2] = cont[cb + 2];
    }
    __syncthreads();
    size_t base = (size_t)t * G_ * B_;
    for (int idx = tid; idx < G_ * B_; idx += 256) {
        int b = idx & 63;
        int pcol = idx >> 6;
        float4 w = g_cwb[pcol];
        float v = g_bossT[pcol * 64 + sb[b]] + g_heroT[pcol * 200 + sh[b]]
                + sc[b][0] * w.x + sc[b][1] * w.y + sc[b][2] * w.z + w.w;
        g_xg[base + idx] = v;
    }
}

// ---------------- kernel 3: persistent LSTM recurrence ----------------
// grid = 128, block = 256 (8 warps, ksplit-8), smem = 32KB(W) + 128KB(h/partials) + 4KB(g)
__global__ void __launch_bounds__(256, 1) k_recur() {
    extern __shared__ char smem[];
    float* whs = (float*)smem;                         // [512][16] W (32KB)
    char*  hsm = smem + 32768;                         // [512 rows][256B] h slices / partials (128KB)
    float* gsm = (float*)(smem + 32768 + 131072);      // [16][64] gates (4KB)

    int cta = blockIdx.x, tid = threadIdx.x;
    int w = tid >> 5, lane = tid & 31;
    int bpg = lane & 7, cg = lane >> 3;                // lane tile: 4 cols x 4 bpairs

    // one-time: stage W_h slice
    const float* wsrc = g_wh4 + (size_t)cta * H_ * CPC;
    for (int i = tid; i < H_ * CPC; i += 256) whs[i] = wsrc[i];

    // reduction roles
    int rcol  = tid >> 4;            // 0..15
    int rbpg  = (tid >> 1) & 7;
    int rhalf = tid & 1;
    int rbp   = rbpg * 4 + rhalf * 2;
    int rlane = (rcol >> 2) * 8 + rbpg;
    int rapair = (rcol & 3) * 2 + rhalf;

    // gate roles
    int jj = tid >> 6, bb = tid & 63;
    int hc = cta * 4 + jj;
    int pb = permb(bb);
    float c_state = 0.f;

    uint32_t hsm_s = (uint32_t)__cvta_generic_to_shared(hsm);
    uint32_t myslice = hsm_s + w * 16384;
    unsigned* myflag = g_barS + w;
    unsigned* arrflag = g_barS + (cta >> 4);
    __syncthreads();

    for (int t = 0; t < T_; ++t) {
        // -------- per-warp wait: my h slice (rows w*64..w*64+63) ready --------
        if (t > 0) {
            if (lane == 0) {
                unsigned tgt = 16u * (unsigned)t;
                unsigned v;
                do {
                    asm volatile("ld.acquire.gpu.global.u32 %0, [%1];" : "=r"(v) : "l"(myflag));
                } while (v < tgt);
            }
            __syncwarp();
        }

        // -------- async-load own 16KB k-slice, 4 pipelined groups of 4KB --------
        const char* src = (const char*)g_hbuf[t & 1] + w * 16384;
        #pragma unroll
        for (int g = 0; g < 4; ++g) {
            #pragma unroll
            for (int i = 0; i < 8; ++i) {
                int off = g * 4096 + i * 512 + lane * 16;
                cp16(myslice + off, src + off);
            }
            cpcommit();
        }

        // xg prefetch (streamed, consumed in reduction)
        size_t xoff = ((size_t)t * G_ + cta * CPC + rcol) * B_ + rbp * 2;
        float4 xv = __ldcs((const float4*)(g_xg + xoff));

        ull acc[16];
        #pragma unroll
        for (int a = 0; a < 16; ++a) acc[a] = 0ull;

        const char* hp = hsm + w * 16384 + bpg * 16;
        const char* wp = (const char*)whs + (w * 64) * 64 + cg * 16;

        // -------- GEMM over own 64-k slice --------
        #pragma unroll
        for (int g = 0; g < 4; ++g) {
            if      (g == 0) cpwait<3>();
            else if (g == 1) cpwait<2>();
            else if (g == 2) cpwait<1>();
            else             cpwait<0>();
            __syncwarp();
            #pragma unroll 4
            for (int kk = 0; kk < 16; ++kk) {
                ulonglong2 h01 = *(const ulonglong2*)(hp);        // bpairs 0,1 of tile
                ulonglong2 h23 = *(const ulonglong2*)(hp + 128);  // bpairs 2,3
                float4 wv = *(const float4*)(wp);                 // 4 cols
                ull wa = pk2(wv.x, wv.x), wb = pk2(wv.y, wv.y);
                ull wc = pk2(wv.z, wv.z), wd = pk2(wv.w, wv.w);
                fma2(acc[0],  h01.x, wa); fma2(acc[1],  h01.y, wa);
                fma2(acc[2],  h23.x, wa); fma2(acc[3],  h23.y, wa);
                fma2(acc[4],  h01.x, wb); fma2(acc[5],  h01.y, wb);
                fma2(acc[6],  h23.x, wb); fma2(acc[7],  h23.y, wb);
                fma2(acc[8],  h01.x, wc); fma2(acc[9],  h01.y, wc);
                fma2(acc[10], h23.x, wc); fma2(acc[11], h23.y, wc);
                fma2(acc[12], h01.x, wd); fma2(acc[13], h01.y, wd);
                fma2(acc[14], h23.x, wd); fma2(acc[15], h23.y, wd);
                hp += 256; wp += 64;
            }
        }

        // -------- store partials into own slice (done reading it) --------
        #pragma unroll
        for (int ap = 0; ap < 8; ++ap) {
            *(ulonglong2*)(hsm + w * 16384 + ap * 512 + lane * 16) =
                make_ulonglong2(acc[2 * ap], acc[2 * ap + 1]);
        }
        __syncthreads();

        // -------- ksplit reduction (+ xg) -> gsm --------
        {
            ull s0 = 0ull, s1 = 0ull;
            #pragma unroll
            for (int ww = 0; ww < 8; ++ww) {
                ulonglong2 p = *(const ulonglong2*)(hsm + ww * 16384 + rapair * 512 + rlane * 16);
                add2(s0, p.x); add2(s1, p.y);
            }
            add2(s0, pk2(xv.x, xv.y));
            add2(s1, pk2(xv.z, xv.w));
            float2 f0 = upk(s0), f1 = upk(s1);
            *(float4*)&gsm[rcol * 64 + rbp * 2] = make_float4(f0.x, f0.y, f1.x, f1.y);
        }
        __syncthreads();

        // -------- gates + state update --------
        float gi = gsm[(0 * 4 + jj) * B_ + bb];
        float gf = gsm[(1 * 4 + jj) * B_ + bb];
        float gg = gsm[(2 * 4 + jj) * B_ + bb];
        float go = gsm[(3 * 4 + jj) * B_ + bb];
        float iv = sigf(gi), fv = sigf(gf), gv = tanha(gg), ov = sigf(go);
        c_state = fv * c_state + iv * gv;
        float h = ov * tanha(c_state);
        g_hbuf[(t + 1) & 1][hc * B_ + pb] = h;                       // permuted for next step
        g_hs[(size_t)t * (H_ * B_) + hc * B_ + bb] = h;              // natural for MLP

        // -------- arrival: fire-and-forget slice counter --------
        __threadfence();
        __syncthreads();
        if (tid == 0) {
            asm volatile("red.relaxed.gpu.global.add.u32 [%0], %1;" :: "l"(arrflag), "r"(1u));
        }
    }
}

// ---------------- kernel 4: MLP epilogue ----------------
__global__ void __launch_bounds__(256, 1) k_mlp(const float* __restrict__ W1,
                                                const float* __restrict__ b1,
                                                const float* __restrict__ W2,
                                                const float* __restrict__ b2,
                                                float* __restrict__ out) {
    extern __shared__ char smem[];
    float* hsm = (float*)smem;                          // [512][64] 128KB
    float* w1c = (float*)(smem + 131072);               // [64][256] 64KB
    float* b1s = (float*)(smem + 131072 + 65536);       // 256
    float* w2s = b1s + 256;                             // 256
    float* red = w2s + 256;                             // [16][64]

    int t = blockIdx.x, tid = threadIdx.x;

    const float4* hsrc = (const float4*)(g_hs + (size_t)t * (H_ * B_));
    float4* hd = (float4*)hsm;
    for (int i = tid; i < H_ * B_ / 4; i += 256) hd[i] = hsrc[i];
    b1s[tid] = b1[tid];
    w2s[tid] = W2[tid];
    __syncthreads();

    int bt = tid & 15, mt = tid >> 4;
    int b0 = bt * 4, m0 = mt * 16;

    ull acc[16][2];
    #pragma unroll
    for (int m = 0; m < 16; ++m) {
        float bv = b1s[m0 + m];
        acc[m][0] = pk2(bv, bv);
        acc[m][1] = pk2(bv, bv);
    }

    for (int kc = 0; kc < 8; ++kc) {
        if (kc > 0) __syncthreads();
        const float4* wsrc = (const float4*)(W1 + (size_t)kc * 64 * 256);
        for (int i = tid; i < 4096; i += 256) ((float4*)w1c)[i] = wsrc[i];
        __syncthreads();
        #pragma unroll 4
        for (int k = 0; k < 64; ++k) {
            const ull* hp = (const ull*)&hsm[(kc * 64 + k) * B_ + b0];
            ull h01 = hp[0], h23 = hp[1];
            const float* wr = &w1c[k * 256 + m0];
            #pragma unroll
            for (int m4 = 0; m4 < 4; ++m4) {
                float4 wv = *(const float4*)&wr[m4 * 4];
                ull wa = pk2(wv.x, wv.x), wb = pk2(wv.y, wv.y);
                ull wc = pk2(wv.z, wv.z), wd = pk2(wv.w, wv.w);
                fma2(acc[m4 * 4 + 0][0], h01, wa); fma2(acc[m4 * 4 + 0][1], h23, wa);
                fma2(acc[m4 * 4 + 1][0], h01, wb); fma2(acc[m4 * 4 + 1][1], h23, wb);
                fma2(acc[m4 * 4 + 2][0], h01, wc); fma2(acc[m4 * 4 + 2][1], h23, wc);
                fma2(acc[m4 * 4 + 3][0], h01, wd); fma2(acc[m4 * 4 + 3][1], h23, wd);
            }
        }
    }

    float p0 = 0.f, p1 = 0.f, p2 = 0.f, p3 = 0.f;
    #pragma unroll
    for (int m = 0; m < 16; ++m) {
        float2 v0 = upk(acc[m][0]), v1 = upk(acc[m][1]);
        float wv = w2s[m0 + m];
        p0 += fmaxf(v0.x, 0.f) * wv;
        p1 += fmaxf(v0.y, 0.f) * wv;
        p2 += fmaxf(v1.x, 0.f) * wv;
        p3 += fmaxf(v1.y, 0.f) * wv;
    }
    red[mt * B_ + b0 + 0] = p0;
    red[mt * B_ + b0 + 1] = p1;
    red[mt * B_ + b0 + 2] = p2;
    red[mt * B_ + b0 + 3] = p3;
    __syncthreads();
    if (tid < B_) {
        float s = b2[0];
        #pragma unroll
        for (int q = 0; q < 16; ++q) s += red[q * B_ + tid];
        out[(size_t)tid * T_ + t] = s;
    }
}

// ---------------- launch ----------------
extern "C" void kernel_launch(void* const* d_in, const int* in_sizes, int n_in,
                              void* d_out, int out_size) {
    const int*   boss_anim  = (const int*)d_in[0];
    const int*   hero_anim  = (const int*)d_in[1];
    const float* continuous = (const float*)d_in[2];
    const float* boss_table = (const float*)d_in[3];
    const float* hero_table = (const float*)d_in[4];
    const float* W_i        = (const float*)d_in[5];
    const float* W_h        = (const float*)d_in[6];
    const float* b_lstm     = (const float*)d_in[7];
    const float* W1         = (const float*)d_in[8];
    const float* b1         = (const float*)d_in[9];
    const float* W2         = (const float*)d_in[10];
    const float* b2         = (const float*)d_in[11];
    float* out = (float*)d_out;

    static bool attr_done = false;
    if (!attr_done) {
        cudaFuncSetAttribute(k_recur, cudaFuncAttributeMaxDynamicSharedMemorySize, 32768 + 131072 + 4096);
        cudaFuncSetAttribute(k_mlp,   cudaFuncAttributeMaxDynamicSharedMemorySize, 131072 + 65536 + 2048 + 4096);
        attr_done = true;
    }

    k_init<<<32, 256>>>();
    k_prep<<<G_, 256>>>(boss_table, hero_table, W_i, W_h, b_lstm);
    k_xg<<<T_, 256>>>(boss_anim, hero_anim, continuous);
    k_recur<<<NCTA, 256, 32768 + 131072 + 4096>>>();
    k_mlp<<<T_, 256, 131072 + 65536 + 2048 + 4096>>>(W1, b1, W2, b2, out);
}

// round 6
// speedup vs baseline: 2.1733x; 2.1733x over previous
#include <cuda_runtime.h>
#include <cuda_bf16.h>
#include <cstdint>

typedef unsigned long long ull;

#define B_    64
#define T_    2048
#define H_    512
#define G_    2048      // 4*H
#define NCTA  128       // persistent CTAs, each owns 4 h-cols = 16 gate cols
#define CPC   16        // gate cols per CTA

// ---------------- device scratch (static, allowed) ----------------
__device__ __align__(16) float  g_xg[(size_t)T_ * G_ * B_];      // 1 GiB  [t][pcol][b]
__device__ __align__(16) float  g_hs[(size_t)T_ * H_ * B_];      // 256 MB [t][k][b] natural
__device__ __align__(16) float2 g_whdup[NCTA * H_ * CPC];        // 8 MB, duplicated W_h, permuted
__device__ __align__(16) float  g_bossT[G_ * 64];                // [pcol][vocab(pad64)]
__device__ __align__(16) float  g_heroT[G_ * 200];               // [pcol][vocab200]
__device__ __align__(16) float4 g_cwb[G_];                       // (Wc0,Wc1,Wc2,bias) permuted
__device__ __align__(16) float  g_hbuf[2][H_ * B_];              // double-buffered h [k][permuted b]
__device__ unsigned g_bar;

// ---------------- helpers ----------------
__device__ __forceinline__ ull pk2(float x, float y) {
    ull r; asm("mov.b64 %0, {%1,%2};" : "=l"(r) : "f"(x), "f"(y)); return r;
}
__device__ __forceinline__ float2 upk(ull v) {
    float2 f; asm("mov.b64 {%0,%1}, %2;" : "=f"(f.x), "=f"(f.y) : "l"(v)); return f;
}
__device__ __forceinline__ void fma2(ull& d, ull a, ull b) {
    asm("fma.rn.f32x2 %0, %1, %2, %3;" : "=l"(d) : "l"(a), "l"(b), "l"(d));
}
__device__ __forceinline__ void cp16(uint32_t s, const void* g) {
    asm volatile("cp.async.cg.shared.global [%0], [%1], 16;" :: "r"(s), "l"(g) : "memory");
}
__device__ __forceinline__ void cpcommit() { asm volatile("cp.async.commit_group;" ::: "memory"); }
template <int N> __device__ __forceinline__ void cpwait() {
    asm volatile("cp.async.wait_group %0;" :: "n"(N) : "memory");
}
__device__ __forceinline__ float sigf(float x) { return 1.0f / (1.0f + __expf(-x)); }
__device__ __forceinline__ float tanha(float x) {
    float r; asm("tanh.approx.f32 %0, %1;" : "=f"(r) : "f"(x)); return r;
}

// b-permutation for h rows (bank-conflict-free GEMM loads)
__device__ __forceinline__ int permb(int b) {
    int q = b >> 2;
    return (((q & 1) * 8) + (q >> 1)) * 4 + (b & 3);
}

// pcol = cta*16 + gate*4 + j  <->  orig gate col = gate*512 + cta*4 + j
__device__ __forceinline__ int orig_col(int pcol) {
    int cta = pcol >> 4, r = pcol & 15, gate = r >> 2, j = r & 3;
    return gate * H_ + cta * 4 + j;
}

// ---------------- kernel 0: init ----------------
__global__ void k_init() {
    int tid = threadIdx.x + blockIdx.x * blockDim.x;
    if (tid == 0) g_bar = 0u;
    for (int i = tid; i < H_ * B_; i += blockDim.x * gridDim.x) {
        g_hbuf[0][i] = 0.f;
        g_hbuf[1][i] = 0.f;
    }
}

// ---------------- kernel 1: projections + weight permute ----------------
__global__ void k_prep(const float* __restrict__ boss_table,
                       const float* __restrict__ hero_table,
                       const float* __restrict__ W_i,
                       const float* __restrict__ W_h,
                       const float* __restrict__ b_lstm) {
    int pcol = blockIdx.x;
    int o = orig_col(pcol);
    int tid = threadIdx.x;

    if (tid < 50) {
        float s = 0.f;
        #pragma unroll
        for (int e = 0; e < 32; ++e) s += boss_table[tid * 32 + e] * W_i[e * G_ + o];
        g_bossT[pcol * 64 + tid] = s;
    } else if (tid < 250) {
        int v = tid - 50;
        float s = 0.f;
        #pragma unroll
        for (int e = 0; e < 32; ++e) s += hero_table[v * 32 + e] * W_i[(32 + e) * G_ + o];
        g_heroT[pcol * 200 + v] = s;
    } else if (tid == 250) {
        g_cwb[pcol] = make_float4(W_i[64 * G_ + o], W_i[65 * G_ + o], W_i[66 * G_ + o], b_lstm[o]);
    }
    int cta = pcol >> 4, r = pcol & 15;
    for (int k = tid; k < H_; k += 256) {
        float w = W_h[k * G_ + o];
        g_whdup[(cta * H_ + k) * CPC + r] = make_float2(w, w);
    }
}

// ---------------- kernel 2: build xg[t][pcol][b] ----------------
__global__ void k_xg(const int* __restrict__ boss_anim,
                     const int* __restrict__ hero_anim,
                     const float* __restrict__ cont) {
    __shared__ int   sb[B_], sh[B_];
    __shared__ float sc[B_][3];
    int t = blockIdx.x, tid = threadIdx.x;
    if (tid < B_) {
        int b = tid;
        int bi = boss_anim[b * T_ + t]; bi = min(max(bi, 0), 49);
        int hi = hero_anim[b * T_ + t]; hi = min(max(hi, 0), 199);
        sb[b] = bi; sh[b] = hi;
        size_t cb = ((size_t)b * T_ + t) * 3;
        sc[b][0] = cont[cb + 0]; sc[b][1] = cont[cb + 1]; sc[b][2] = cont[cb + 2];
    }
    __syncthreads();
    size_t base = (size_t)t * G_ * B_;
    for (int idx = tid; idx < G_ * B_; idx += 256) {
        int b = idx & 63;
        int pcol = idx >> 6;
        float4 w = g_cwb[pcol];
        float v = g_bossT[pcol * 64 + sb[b]] + g_heroT[pcol * 200 + sh[b]]
                + sc[b][0] * w.x + sc[b][1] * w.y + sc[b][2] * w.z + w.w;
        g_xg[base + idx] = v;
    }
}

// ---------------- kernel 3: persistent LSTM recurrence ----------------
// grid = 128, block = 256 (8 warps, ksplit-8), smem = 64KB(Wdup) + 128KB(h/partials)
__global__ void __launch_bounds__(256, 1) k_recur() {
    extern __shared__ char smem[];
    float2* whs = (float2*)smem;                       // [512][16] duplicated W (64KB)
    char*   hsm = smem + 65536;                        // [512 rows][256B] h slices / partials (128KB)

    int cta = blockIdx.x, tid = threadIdx.x;
    int w = tid >> 5, lane = tid & 31;
    int bpg = lane & 7, cg = lane >> 3;                // lane tile: 4 cols x 4 bpairs

    // one-time: stage W_h slice
    const float2* wsrc = g_whdup + (size_t)cta * H_ * CPC;
    for (int i = tid; i < H_ * CPC; i += 256) whs[i] = wsrc[i];

    // gate roles (also reduction roles: thread = (jj, bb))
    int jj = tid >> 6, bb = tid & 63;
    int hc = cta * 4 + jj;
    int pb = permb(bb);
    float c_state = 0.f;

    uint32_t hsm_s = (uint32_t)__cvta_generic_to_shared(hsm);
    uint32_t myslice = hsm_s + w * 16384;
    __syncthreads();

    for (int t = 0; t < T_; ++t) {
        // -------- async-load own 16KB k-slice, 4 pipelined groups of 4KB --------
        const char* src = (const char*)g_hbuf[t & 1] + w * 16384;
        #pragma unroll
        for (int g = 0; g < 4; ++g) {
            #pragma unroll
            for (int i = 0; i < 8; ++i) {
                int off = g * 4096 + i * 512 + lane * 16;
                cp16(myslice + off, src + off);
            }
            cpcommit();
        }

        // xg prefetch: 4 gate values for (jj, bb), coalesced per warp
        float xv0 = __ldcs(g_xg + ((size_t)t * G_ + cta * CPC + 0 * 4 + jj) * B_ + bb);
        float xv1 = __ldcs(g_xg + ((size_t)t * G_ + cta * CPC + 1 * 4 + jj) * B_ + bb);
        float xv2 = __ldcs(g_xg + ((size_t)t * G_ + cta * CPC + 2 * 4 + jj) * B_ + bb);
        float xv3 = __ldcs(g_xg + ((size_t)t * G_ + cta * CPC + 3 * 4 + jj) * B_ + bb);

        ull acc[16];
        #pragma unroll
        for (int a = 0; a < 16; ++a) acc[a] = 0ull;

        const char* hp = hsm + w * 16384 + bpg * 16;
        const char* wp = (const char*)whs + (w * 64) * 128 + cg * 32;

        // -------- GEMM over own 64-k slice --------
        #pragma unroll
        for (int g = 0; g < 4; ++g) {
            if      (g == 0) cpwait<3>();
            else if (g == 1) cpwait<2>();
            else if (g == 2) cpwait<1>();
            else             cpwait<0>();
            __syncwarp();
            #pragma unroll 4
            for (int kk = 0; kk < 16; ++kk) {
                ulonglong2 h01 = *(const ulonglong2*)(hp);        // bpairs 0,1 of tile
                ulonglong2 h23 = *(const ulonglong2*)(hp + 128);  // bpairs 2,3
                ulonglong2 w01 = *(const ulonglong2*)(wp);        // dup cols 0,1
                ulonglong2 w23 = *(const ulonglong2*)(wp + 16);   // dup cols 2,3
                fma2(acc[0],  h01.x, w01.x); fma2(acc[1],  h01.y, w01.x);
                fma2(acc[2],  h23.x, w01.x); fma2(acc[3],  h23.y, w01.x);
                fma2(acc[4],  h01.x, w01.y); fma2(acc[5],  h01.y, w01.y);
                fma2(acc[6],  h23.x, w01.y); fma2(acc[7],  h23.y, w01.y);
                fma2(acc[8],  h01.x, w23.x); fma2(acc[9],  h01.y, w23.x);
                fma2(acc[10], h23.x, w23.x); fma2(acc[11], h23.y, w23.x);
                fma2(acc[12], h01.x, w23.y); fma2(acc[13], h01.y, w23.y);
                fma2(acc[14], h23.x, w23.y); fma2(acc[15], h23.y, w23.y);
                hp += 256; wp += 128;
            }
        }
        // acc[a]: a = ci*4 + bpi -> (col cg*4+ci, bpair bpg*4+bpi), packed {b even, b odd}

        // -------- store partials into own slice as [16 cols][64 b] floats --------
        // addr = w*16384 + col*256 + bpair*8 ; acc[ci*4+bpi] pairs are 32B contiguous
        #pragma unroll
        for (int ci = 0; ci < 4; ++ci) {
            char* pbase = hsm + w * 16384 + (cg * 4 + ci) * 256 + bpg * 32;
            *(ulonglong2*)(pbase)      = make_ulonglong2(acc[ci * 4 + 0], acc[ci * 4 + 1]);
            *(ulonglong2*)(pbase + 16) = make_ulonglong2(acc[ci * 4 + 2], acc[ci * 4 + 3]);
        }
        __syncthreads();

        // -------- fused ksplit reduction + gates (thread = (jj, bb)) --------
        float gsum[4];
        #pragma unroll
        for (int g0 = 0; g0 < 4; ++g0) {
            int pcol = g0 * 4 + jj;
            float s = 0.f;
            #pragma unroll
            for (int ww = 0; ww < 8; ++ww)
                s += *(const float*)(hsm + ww * 16384 + pcol * 256 + bb * 4);
            gsum[g0] = s;
        }
        float gi = gsum[0] + xv0;
        float gf = gsum[1] + xv1;
        float gg = gsum[2] + xv2;
        float go = gsum[3] + xv3;
        float iv = sigf(gi), fv = sigf(gf), gv = tanha(gg), ov = sigf(go);
        c_state = fv * c_state + iv * gv;
        float h = ov * tanha(c_state);
        g_hbuf[(t + 1) & 1][hc * B_ + pb] = h;                       // permuted for next step
        g_hs[(size_t)t * (H_ * B_) + hc * B_ + bb] = h;              // natural for MLP

        // -------- grid barrier (proven round-4 form) --------
        __threadfence();
        __syncthreads();
        if (tid == 0) {
            atomicAdd(&g_bar, 1u);
            unsigned tgt = (unsigned)NCTA * (unsigned)(t + 1);
            while (*(volatile unsigned*)&g_bar < tgt) { }
            __threadfence();
        }
        __syncthreads();
    }
}

// ---------------- kernel 4: MLP epilogue ----------------
__global__ void __launch_bounds__(256, 1) k_mlp(const float* __restrict__ W1,
                                                const float* __restrict__ b1,
                                                const float* __restrict__ W2,
                                                const float* __restrict__ b2,
                                                float* __restrict__ out) {
    extern __shared__ char smem[];
    float* hsm = (float*)smem;                          // [512][64] 128KB
    float* w1c = (float*)(smem + 131072);               // [64][256] 64KB
    float* b1s = (float*)(smem + 131072 + 65536);       // 256
    float* w2s = b1s + 256;                             // 256
    float* red = w2s + 256;                             // [16][64]

    int t = blockIdx.x, tid = threadIdx.x;

    const float4* hsrc = (const float4*)(g_hs + (size_t)t * (H_ * B_));
    float4* hd = (float4*)hsm;
    for (int i = tid; i < H_ * B_ / 4; i += 256) hd[i] = hsrc[i];
    b1s[tid] = b1[tid];
    w2s[tid] = W2[tid];
    __syncthreads();

    int bt = tid & 15, mt = tid >> 4;
    int b0 = bt * 4, m0 = mt * 16;

    ull acc[16][2];
    #pragma unroll
    for (int m = 0; m < 16; ++m) {
        float bv = b1s[m0 + m];
        acc[m][0] = pk2(bv, bv);
        acc[m][1] = pk2(bv, bv);
    }

    for (int kc = 0; kc < 8; ++kc) {
        if (kc > 0) __syncthreads();
        const float4* wsrc = (const float4*)(W1 + (size_t)kc * 64 * 256);
        for (int i = tid; i < 4096; i += 256) ((float4*)w1c)[i] = wsrc[i];
        __syncthreads();
        #pragma unroll 4
        for (int k = 0; k < 64; ++k) {
            const ull* hp = (const ull*)&hsm[(kc * 64 + k) * B_ + b0];
            ull h01 = hp[0], h23 = hp[1];
            const float* wr = &w1c[k * 256 + m0];
            #pragma unroll
            for (int m4 = 0; m4 < 4; ++m4) {
                float4 wv = *(const float4*)&wr[m4 * 4];
                ull wa = pk2(wv.x, wv.x), wb = pk2(wv.y, wv.y);
                ull wc = pk2(wv.z, wv.z), wd = pk2(wv.w, wv.w);
                fma2(acc[m4 * 4 + 0][0], h01, wa); fma2(acc[m4 * 4 + 0][1], h23, wa);
                fma2(acc[m4 * 4 + 1][0], h01, wb); fma2(acc[m4 * 4 + 1][1], h23, wb);
                fma2(acc[m4 * 4 + 2][0], h01, wc); fma2(acc[m4 * 4 + 2][1], h23, wc);
                fma2(acc[m4 * 4 + 3][0], h01, wd); fma2(acc[m4 * 4 + 3][1], h23, wd);
            }
        }
    }

    float p0 = 0.f, p1 = 0.f, p2 = 0.f, p3 = 0.f;
    #pragma unroll
    for (int m = 0; m < 16; ++m) {
        float2 v0 = upk(acc[m][0]), v1 = upk(acc[m][1]);
        float wv = w2s[m0 + m];
        p0 += fmaxf(v0.x, 0.f) * wv;
        p1 += fmaxf(v0.y, 0.f) * wv;
        p2 += fmaxf(v1.x, 0.f) * wv;
        p3 += fmaxf(v1.y, 0.f) * wv;
    }
    red[mt * B_ + b0 + 0] = p0;
    red[mt * B_ + b0 + 1] = p1;
    red[mt * B_ + b0 + 2] = p2;
    red[mt * B_ + b0 + 3] = p3;
    __syncthreads();
    if (tid < B_) {
        float s = b2[0];
        #pragma unroll
        for (int q = 0; q < 16; ++q) s += red[q * B_ + tid];
        out[(size_t)tid * T_ + t] = s;
    }
}

// ---------------- launch ----------------
extern "C" void kernel_launch(void* const* d_in, const int* in_sizes, int n_in,
                              void* d_out, int out_size) {
    const int*   boss_anim  = (const int*)d_in[0];
    const int*   hero_anim  = (const int*)d_in[1];
    const float* continuous = (const float*)d_in[2];
    const float* boss_table = (const float*)d_in[3];
    const float* hero_table = (const float*)d_in[4];
    const float* W_i        = (const float*)d_in[5];
    const float* W_h        = (const float*)d_in[6];
    const float* b_lstm     = (const float*)d_in[7];
    const float* W1         = (const float*)d_in[8];
    const float* b1         = (const float*)d_in[9];
    const float* W2         = (const float*)d_in[10];
    const float* b2         = (const float*)d_in[11];
    float* out = (float*)d_out;

    static bool attr_done = false;
    if (!attr_done) {
        cudaFuncSetAttribute(k_recur, cudaFuncAttributeMaxDynamicSharedMemorySize, 65536 + 131072);
        cudaFuncSetAttribute(k_mlp,   cudaFuncAttributeMaxDynamicSharedMemorySize, 131072 + 65536 + 2048 + 4096);
        attr_done = true;
    }

    k_init<<<32, 256>>>();
    k_prep<<<G_, 256>>>(boss_table, hero_table, W_i, W_h, b_lstm);
    k_xg<<<T_, 256>>>(boss_anim, hero_anim, continuous);
    k_recur<<<NCTA, 256, 65536 + 131072>>>();
    k_mlp<<<T_, 256, 131072 + 65536 + 2048 + 4096>>>(W1, b1, W2, b2, out);
}

// round 7
// speedup vs baseline: 2.5505x; 1.1735x over previous
#include <cuda_runtime.h>
#include <cuda_bf16.h>
#include <cstdint>

typedef unsigned long long ull;

#define B_    64
#define T_    2048
#define H_    512
#define G_    2048      // 4*H
#define NCTA  128       // 4 groups x 32 CTAs
#define GCTA  32        // CTAs per group
#define GB    16        // batches per group
#define LC    64        // gate cols per CTA

// ---------------- device scratch (static, allowed) ----------------
__device__ __align__(16) float  g_xg[(size_t)T_ * NCTA * LC * GB]; // 1 GiB [t][cta][lc][b2]
__device__ __align__(16) float  g_hs[(size_t)T_ * H_ * B_];        // 256 MB [t][k][b] natural
__device__ __align__(16) float  g_whP[GCTA * H_ * LC];             // 4 MB [ci][k][lc]
__device__ __align__(16) float  g_bossT[G_ * 64];                  // [o][vocab pad64]
__device__ __align__(16) float  g_heroT[G_ * 200];                 // [o][vocab200]
__device__ __align__(16) float4 g_cwb[G_];                         // (Wc0,Wc1,Wc2,bias) by o
__device__ __align__(16) float  g_hbufG[4 * 2 * H_ * GB];          // per-group double-buffered h
__device__ unsigned g_barG[4 * 32];                                // per-group counters, 128B apart

// ---------------- helpers ----------------
__device__ __forceinline__ ull pk2(float x, float y) {
    ull r; asm("mov.b64 %0, {%1,%2};" : "=l"(r) : "f"(x), "f"(y)); return r;
}
__device__ __forceinline__ float2 upk(ull v) {
    float2 f; asm("mov.b64 {%0,%1}, %2;" : "=f"(f.x), "=f"(f.y) : "l"(v)); return f;
}
__device__ __forceinline__ void fma2(ull& d, ull a, ull b) {
    asm("fma.rn.f32x2 %0, %1, %2, %3;" : "=l"(d) : "l"(a), "l"(b), "l"(d));
}
__device__ __forceinline__ void cp16(uint32_t s, const void* g) {
    asm volatile("cp.async.cg.shared.global [%0], [%1], 16;" :: "r"(s), "l"(g) : "memory");
}
__device__ __forceinline__ void cpcommit() { asm volatile("cp.async.commit_group;" ::: "memory"); }
template <int N> __device__ __forceinline__ void cpwait() {
    asm volatile("cp.async.wait_group %0;" :: "n"(N) : "memory");
}
__device__ __forceinline__ float sigf(float x) { return 1.0f / (1.0f + __expf(-x)); }
__device__ __forceinline__ float tanha(float x) {
    float r; asm("tanh.approx.f32 %0, %1;" : "=f"(r) : "f"(x)); return r;
}

// ---------------- kernel 0: init ----------------
__global__ void k_init() {
    int tid = threadIdx.x + blockIdx.x * blockDim.x;
    if (tid < 4 * 32) g_barG[tid] = 0u;
    for (int i = tid; i < 4 * 2 * H_ * GB; i += blockDim.x * gridDim.x)
        g_hbufG[i] = 0.f;
}

// ---------------- kernel 1: embedding/continuous projections (by orig col o) ----
__global__ void k_prep(const float* __restrict__ boss_table,
                       const float* __restrict__ hero_table,
                       const float* __restrict__ W_i,
                       const float* __restrict__ b_lstm) {
    int o = blockIdx.x;
    int tid = threadIdx.x;
    if (tid < 50) {
        float s = 0.f;
        #pragma unroll
        for (int e = 0; e < 32; ++e) s += boss_table[tid * 32 + e] * W_i[e * G_ + o];
        g_bossT[o * 64 + tid] = s;
    } else if (tid < 250) {
        int v = tid - 50;
        float s = 0.f;
        #pragma unroll
        for (int e = 0; e < 32; ++e) s += hero_table[v * 32 + e] * W_i[(32 + e) * G_ + o];
        g_heroT[o * 200 + v] = s;
    } else if (tid == 250) {
        g_cwb[o] = make_float4(W_i[64 * G_ + o], W_i[65 * G_ + o], W_i[66 * G_ + o], b_lstm[o]);
    }
}

// ---------------- kernel 1b: W_h permute -> whP[ci][k][lc] ----------------
// grid = 512 blocks: (ci in 32) x (kb in 16); 256 threads: 32 k x 8 lc-groups
__global__ void k_prepW(const float* __restrict__ W_h) {
    int ci = blockIdx.x >> 4, kb = blockIdx.x & 15;
    int tid = threadIdx.x;
    int k = kb * 32 + (tid >> 3);
    int lc0 = (tid & 7) * 8;
    #pragma unroll
    for (int l = 0; l < 8; ++l) {
        int lc = lc0 + l;
        int gate = lc >> 4, j = lc & 15;
        int o = gate * H_ + ci * 16 + j;
        g_whP[((size_t)ci * H_ + k) * LC + lc] = W_h[(size_t)k * G_ + o];
    }
}

// ---------------- kernel 2: build xg[t][cta][lc][b2] ----------------
__global__ void k_xg(const int* __restrict__ boss_anim,
                     const int* __restrict__ hero_anim,
                     const float* __restrict__ cont) {
    __shared__ int   sb[B_], sh[B_];
    __shared__ float sc[B_][3];
    int t = blockIdx.x, tid = threadIdx.x;
    if (tid < B_) {
        int b = tid;
        int bi = boss_anim[b * T_ + t]; bi = min(max(bi, 0), 49);
        int hi = hero_anim[b * T_ + t]; hi = min(max(hi, 0), 199);
        sb[b] = bi; sh[b] = hi;
        size_t cb = ((size_t)b * T_ + t) * 3;
        sc[b][0] = cont[cb + 0]; sc[b][1] = cont[cb + 1]; sc[b][2] = cont[cb + 2];
    }
    __syncthreads();
    size_t base = (size_t)t * (NCTA * LC * GB);
    for (int idx = tid; idx < NCTA * LC * GB; idx += 256) {
        int cta = idx >> 10;
        int lc  = (idx >> 4) & 63;
        int b2  = idx & 15;
        int gp = cta >> 5, ci = cta & 31;
        int gate = lc >> 4, j = lc & 15;
        int o = gate * H_ + ci * 16 + j;
        int b = gp * GB + b2;
        float4 w = g_cwb[o];
        float v = g_bossT[o * 64 + sb[b]] + g_heroT[o * 200 + sh[b]]
                + sc[b][0] * w.x + sc[b][1] * w.y + sc[b][2] * w.z + w.w;
        g_xg[base + idx] = v;
    }
}

// ---------------- kernel 3: persistent LSTM recurrence (grouped) ----------------
// grid = 128 (4 groups x 32), block = 256 (8 warps, ksplit-8)
// smem: W 128KB + h 32KB + partials 34816B = 198656B
#define SM_W    0
#define SM_H    131072
#define SM_P    (131072 + 32768)
#define PS_     4352            // partial stride per warp: 16 rows x 272B
__global__ void __launch_bounds__(256, 1) k_recur() {
    extern __shared__ char smem[];
    char* whsB = smem + SM_W;           // [512][256B]
    char* hsmB = smem + SM_H;           // [512][64B]
    char* part = smem + SM_P;           // [8][16][272B]

    int cta = blockIdx.x, tid = threadIdx.x;
    int w = tid >> 5, lane = tid & 31;
    int cg = lane & 7, bg = lane >> 3;  // 8 col-groups x 4 batch-groups
    int gp = cta >> 5, ci = cta & 31;

    // one-time: stage W slice (shared by same-ci CTAs of all groups)
    {
        const float4* wsrc = (const float4*)(g_whP + (size_t)ci * H_ * LC);
        float4* wdst = (float4*)whsB;
        for (int i = tid; i < H_ * LC / 4; i += 256) wdst[i] = wsrc[i];
    }

    // reduce/gate roles: thread = (j in 16 h-cols, b2 in 16 batches)
    int j = tid >> 4, b2 = tid & 15;
    float c_state = 0.f;

    uint32_t hsm_s = (uint32_t)__cvta_generic_to_shared(hsmB);
    float* hbuf0 = g_hbufG + (size_t)gp * 2 * H_ * GB;
    unsigned* bar = g_barG + gp * 32;
    __syncthreads();

    for (int t = 0; t < T_; ++t) {
        // -------- async-load own 4KB k-slice (rows w*64..w*64+64) --------
        const char* src = (const char*)(hbuf0 + (size_t)(t & 1) * H_ * GB) + w * 4096;
        uint32_t dst = hsm_s + w * 4096;
        #pragma unroll
        for (int i = 0; i < 4; ++i) cp16(dst + i * 512 + lane * 16, src + i * 512 + lane * 16);
        cpcommit();
        #pragma unroll
        for (int i = 4; i < 8; ++i) cp16(dst + i * 512 + lane * 16, src + i * 512 + lane * 16);
        cpcommit();

        // xg prefetch (4 gate values for (j, b2))
        size_t xb = ((size_t)t * NCTA + cta) * (LC * GB);
        float xv0 = __ldcs(g_xg + xb + (0 * 16 + j) * 16 + b2);
        float xv1 = __ldcs(g_xg + xb + (1 * 16 + j) * 16 + b2);
        float xv2 = __ldcs(g_xg + xb + (2 * 16 + j) * 16 + b2);
        float xv3 = __ldcs(g_xg + xb + (3 * 16 + j) * 16 + b2);

        ull acc[16];
        #pragma unroll
        for (int a = 0; a < 16; ++a) acc[a] = 0ull;

        const char* wP = whsB + (w * 64) * 256 + cg * 16;
        const char* hP = hsmB + (w * 64) * 64 + bg * 16;

        #define GBODY                                                          \
        {                                                                      \
            float4 hv = *(const float4*)(hP);                                  \
            ulonglong2 wA = *(const ulonglong2*)(wP);                          \
            ulonglong2 wB = *(const ulonglong2*)(wP + 128);                    \
            ull h0 = pk2(hv.x, hv.x), h1 = pk2(hv.y, hv.y);                    \
            ull h2 = pk2(hv.z, hv.z), h3 = pk2(hv.w, hv.w);                    \
            fma2(acc[0],  wA.x, h0); fma2(acc[1],  wA.x, h1);                  \
            fma2(acc[2],  wA.x, h2); fma2(acc[3],  wA.x, h3);                  \
            fma2(acc[4],  wA.y, h0); fma2(acc[5],  wA.y, h1);                  \
            fma2(acc[6],  wA.y, h2); fma2(acc[7],  wA.y, h3);                  \
            fma2(acc[8],  wB.x, h0); fma2(acc[9],  wB.x, h1);                  \
            fma2(acc[10], wB.x, h2); fma2(acc[11], wB.x, h3);                  \
            fma2(acc[12], wB.y, h0); fma2(acc[13], wB.y, h1);                  \
            fma2(acc[14], wB.y, h2); fma2(acc[15], wB.y, h3);                  \
            wP += 256; hP += 64;                                               \
        }

        cpwait<1>();
        __syncwarp();
        #pragma unroll 8
        for (int k = 0; k < 32; ++k) GBODY
        cpwait<0>();
        __syncwarp();
        #pragma unroll 8
        for (int k = 0; k < 32; ++k) GBODY
        #undef GBODY

        // -------- store partials [w][b2 (pad 272B)][lc] --------
        #pragma unroll
        for (int b = 0; b < 4; ++b) {
            char* pb = part + w * PS_ + (bg * 4 + b) * 272 + cg * 16;
            *(ulonglong2*)(pb)       = make_ulonglong2(acc[0 + b], acc[4 + b]);
            *(ulonglong2*)(pb + 128) = make_ulonglong2(acc[8 + b], acc[12 + b]);
        }
        __syncthreads();

        // -------- fused ksplit reduction + gates --------
        float gs[4];
        #pragma unroll
        for (int g0 = 0; g0 < 4; ++g0) {
            int lc = g0 * 16 + j;
            float s = 0.f;
            #pragma unroll
            for (int w8 = 0; w8 < 8; ++w8)
                s += *(const float*)(part + w8 * PS_ + b2 * 272 + lc * 4);
            gs[g0] = s;
        }
        float gi = gs[0] + xv0, gf = gs[1] + xv1, gg = gs[2] + xv2, go = gs[3] + xv3;
        float iv = sigf(gi), fv = sigf(gf), gv = tanha(gg), ov = sigf(go);
        c_state = fv * c_state + iv * gv;
        float h = ov * tanha(c_state);
        hbuf0[(size_t)((t + 1) & 1) * H_ * GB + (ci * 16 + j) * GB + b2] = h;
        g_hs[((size_t)t * H_ + ci * 16 + j) * B_ + gp * GB + b2] = h;

        // -------- group barrier (32 arrivals, group-local counter) --------
        __threadfence();
        __syncthreads();
        if (tid == 0) {
            atomicAdd(bar, 1u);
            unsigned tgt = (unsigned)GCTA * (unsigned)(t + 1);
            while (*(volatile unsigned*)bar < tgt) { }
            __threadfence();
        }
        __syncthreads();
    }
}

// ---------------- kernel 4: MLP epilogue ----------------
__global__ void __launch_bounds__(256, 1) k_mlp(const float* __restrict__ W1,
                                                const float* __restrict__ b1,
                                                const float* __restrict__ W2,
                                                const float* __restrict__ b2,
                                                float* __restrict__ out) {
    extern __shared__ char smem[];
    float* hsm = (float*)smem;                          // [512][64] 128KB
    float* w1c = (float*)(smem + 131072);               // [64][256] 64KB
    float* b1s = (float*)(smem + 131072 + 65536);       // 256
    float* w2s = b1s + 256;                             // 256
    float* red = w2s + 256;                             // [16][64]

    int t = blockIdx.x, tid = threadIdx.x;

    const float4* hsrc = (const float4*)(g_hs + (size_t)t * (H_ * B_));
    float4* hd = (float4*)hsm;
    for (int i = tid; i < H_ * B_ / 4; i += 256) hd[i] = hsrc[i];
    b1s[tid] = b1[tid];
    w2s[tid] = W2[tid];
    __syncthreads();

    int bt = tid & 15, mt = tid >> 4;
    int b0 = bt * 4, m0 = mt * 16;

    ull acc[16][2];
    #pragma unroll
    for (int m = 0; m < 16; ++m) {
        float bv = b1s[m0 + m];
        acc[m][0] = pk2(bv, bv);
        acc[m][1] = pk2(bv, bv);
    }

    for (int kc = 0; kc < 8; ++kc) {
        if (kc > 0) __syncthreads();
        const float4* wsrc = (const float4*)(W1 + (size_t)kc * 64 * 256);
        for (int i = tid; i < 4096; i += 256) ((float4*)w1c)[i] = wsrc[i];
        __syncthreads();
        #pragma unroll 4
        for (int k = 0; k < 64; ++k) {
            const ull* hp = (const ull*)&hsm[(kc * 64 + k) * B_ + b0];
            ull h01 = hp[0], h23 = hp[1];
            const float* wr = &w1c[k * 256 + m0];
            #pragma unroll
            for (int m4 = 0; m4 < 4; ++m4) {
                float4 wv = *(const float4*)&wr[m4 * 4];
                ull wa = pk2(wv.x, wv.x), wb = pk2(wv.y, wv.y);
                ull wc = pk2(wv.z, wv.z), wd = pk2(wv.w, wv.w);
                fma2(acc[m4 * 4 + 0][0], h01, wa); fma2(acc[m4 * 4 + 0][1], h23, wa);
                fma2(acc[m4 * 4 + 1][0], h01, wb); fma2(acc[m4 * 4 + 1][1], h23, wb);
                fma2(acc[m4 * 4 + 2][0], h01, wc); fma2(acc[m4 * 4 + 2][1], h23, wc);
                fma2(acc[m4 * 4 + 3][0], h01, wd); fma2(acc[m4 * 4 + 3][1], h23, wd);
            }
        }
    }

    float p0 = 0.f, p1 = 0.f, p2 = 0.f, p3 = 0.f;
    #pragma unroll
    for (int m = 0; m < 16; ++m) {
        float2 v0 = upk(acc[m][0]), v1 = upk(acc[m][1]);
        float wv = w2s[m0 + m];
        p0 += fmaxf(v0.x, 0.f) * wv;
        p1 += fmaxf(v0.y, 0.f) * wv;
        p2 += fmaxf(v1.x, 0.f) * wv;
        p3 += fmaxf(v1.y, 0.f) * wv;
    }
    red[mt * B_ + b0 + 0] = p0;
    red[mt * B_ + b0 + 1] = p1;
    red[mt * B_ + b0 + 2] = p2;
    red[mt * B_ + b0 + 3] = p3;
    __syncthreads();
    if (tid < B_) {
        float s = b2[0];
        #pragma unroll
        for (int q = 0; q < 16; ++q) s += red[q * B_ + tid];
        out[(size_t)tid * T_ + t] = s;
    }
}

// ---------------- launch ----------------
extern "C" void kernel_launch(void* const* d_in, const int* in_sizes, int n_in,
                              void* d_out, int out_size) {
    const int*   boss_anim  = (const int*)d_in[0];
    const int*   hero_anim  = (const int*)d_in[1];
    const float* continuous = (const float*)d_in[2];
    const float* boss_table = (const float*)d_in[3];
    const float* hero_table = (const float*)d_in[4];
    const float* W_i        = (const float*)d_in[5];
    const float* W_h        = (const float*)d_in[6];
    const float* b_lstm     = (const float*)d_in[7];
    const float* W1         = (const float*)d_in[8];
    const float* b1         = (const float*)d_in[9];
    const float* W2         = (const float*)d_in[10];
    const float* b2         = (const float*)d_in[11];
    float* out = (float*)d_out;

    static bool attr_done = false;
    if (!attr_done) {
        cudaFuncSetAttribute(k_recur, cudaFuncAttributeMaxDynamicSharedMemorySize, 198656);
        cudaFuncSetAttribute(k_mlp,   cudaFuncAttributeMaxDynamicSharedMemorySize, 131072 + 65536 + 2048 + 4096);
        attr_done = true;
    }

    k_init<<<32, 256>>>();
    k_prep<<<G_, 256>>>(boss_table, hero_table, W_i, b_lstm);
    k_prepW<<<512, 256>>>(W_h);
    k_xg<<<T_, 256>>>(boss_anim, hero_anim, continuous);
    k_recur<<<NCTA, 256, 198656>>>();
    k_mlp<<<T_, 256, 131072 + 65536 + 2048 + 4096>>>(W1, b1, W2, b2, out);
}

// round 9
// speedup vs baseline: 2.6180x; 1.0265x over previous
#include <cuda_runtime.h>
#include <cuda_bf16.h>
#include <cstdint>

typedef unsigned long long ull;

#define B_    64
#define T_    2048
#define H_    512
#define G_    2048      // 4*H
#define NCTA  128       // 4 groups x 32 CTAs
#define GCTA  32        // CTAs per group
#define GB    16        // batches per group
#define LC    64        // gate cols per CTA

// ---------------- device scratch (static, allowed) ----------------
__device__ __align__(16) float  g_hs[(size_t)T_ * H_ * B_];        // 256 MB [t][k][b] natural
__device__ __align__(16) float  g_whP[GCTA * H_ * LC];             // 4 MB [ci][k][lc]
__device__ __align__(16) float  g_bossT4[50 * H_ * 4];             // [v][hcol][gate]
__device__ __align__(16) float  g_heroT4[200 * H_ * 4];            // [v][hcol][gate]
__device__ __align__(16) float4 g_cwb[G_];                         // (Wc0,Wc1,Wc2,bias) by o
__device__ __align__(16) float  g_hbufG[4 * 2 * H_ * GB];          // per-group double-buffered h
__device__ unsigned g_barG[4 * 32];                                // per-group counters, 128B apart

// ---------------- helpers ----------------
__device__ __forceinline__ ull pk2(float x, float y) {
    ull r; asm("mov.b64 %0, {%1,%2};" : "=l"(r) : "f"(x), "f"(y)); return r;
}
__device__ __forceinline__ float2 upk(ull v) {
    float2 f; asm("mov.b64 {%0,%1}, %2;" : "=f"(f.x), "=f"(f.y) : "l"(v)); return f;
}
__device__ __forceinline__ void fma2(ull& d, ull a, ull b) {
    asm("fma.rn.f32x2 %0, %1, %2, %3;" : "=l"(d) : "l"(a), "l"(b), "l"(d));
}
__device__ __forceinline__ void cp16(uint32_t s, const void* g) {
    asm volatile("cp.async.cg.shared.global [%0], [%1], 16;" :: "r"(s), "l"(g) : "memory");
}
__device__ __forceinline__ void cpcommit() { asm volatile("cp.async.commit_group;" ::: "memory"); }
template <int N> __device__ __forceinline__ void cpwait() {
    asm volatile("cp.async.wait_group %0;" :: "n"(N) : "memory");
}
__device__ __forceinline__ float sigf(float x) { return 1.0f / (1.0f + __expf(-x)); }
__device__ __forceinline__ float tanha(float x) {
    float r; asm("tanh.approx.f32 %0, %1;" : "=f"(r) : "f"(x)); return r;
}

// ---------------- kernel 0: init ----------------
__global__ void k_init() {
    int tid = threadIdx.x + blockIdx.x * blockDim.x;
    if (tid < 4 * 32) g_barG[tid] = 0u;
    for (int i = tid; i < 4 * 2 * H_ * GB; i += blockDim.x * gridDim.x)
        g_hbufG[i] = 0.f;
}

// ---------------- kernel 1: projections (gate-packed tables) ----------------
__global__ void k_prep(const float* __restrict__ boss_table,
                       const float* __restrict__ hero_table,
                       const float* __restrict__ W_i,
                       const float* __restrict__ b_lstm) {
    int o = blockIdx.x;
    int gate = o >> 9, hcol = o & 511;
    int tid = threadIdx.x;
    if (tid < 50) {
        float s = 0.f;
        #pragma unroll
        for (int e = 0; e < 32; ++e) s += boss_table[tid * 32 + e] * W_i[e * G_ + o];
        g_bossT4[(tid * H_ + hcol) * 4 + gate] = s;
    } else if (tid < 250) {
        int v = tid - 50;
        float s = 0.f;
        #pragma unroll
        for (int e = 0; e < 32; ++e) s += hero_table[v * 32 + e] * W_i[(32 + e) * G_ + o];
        g_heroT4[(v * H_ + hcol) * 4 + gate] = s;
    } else if (tid == 250) {
        g_cwb[o] = make_float4(W_i[64 * G_ + o], W_i[65 * G_ + o], W_i[66 * G_ + o], b_lstm[o]);
    }
}

// ---------------- kernel 1b: W_h permute -> whP[ci][k][lc] ----------------
__global__ void k_prepW(const float* __restrict__ W_h) {
    int ci = blockIdx.x >> 4, kb = blockIdx.x & 15;
    int tid = threadIdx.x;
    int k = kb * 32 + (tid >> 3);
    int lc0 = (tid & 7) * 8;
    #pragma unroll
    for (int l = 0; l < 8; ++l) {
        int lc = lc0 + l;
        int gate = lc >> 4, j = lc & 15;
        int o = gate * H_ + ci * 16 + j;
        g_whP[((size_t)ci * H_ + k) * LC + lc] = W_h[(size_t)k * G_ + o];
    }
}

// ---------------- kernel 3: persistent LSTM recurrence (R7 skeleton + inline xg) --
#define SM_W    0
#define SM_H    131072
#define SM_P    (131072 + 32768)
#define PS_     4352            // partial stride per warp: 16 rows x 272B
#define SM_STG  (SM_P + 8 * PS_)
#define SMTOT   (SM_STG + 1024)
__global__ void __launch_bounds__(256, 1) k_recur(const int* __restrict__ boss_anim,
                                                  const int* __restrict__ hero_anim,
                                                  const float* __restrict__ cont) {
    extern __shared__ char smem[];
    char* whsB = smem + SM_W;           // [512][256B]
    char* hsmB = smem + SM_H;           // [512][64B]
    char* part = smem + SM_P;           // [8][16][272B]
    int*   ibuf = (int*)(smem + SM_STG);           // [2][16][2]
    float* cbuf = (float*)(smem + SM_STG + 256);   // [2][16][4]

    int cta = blockIdx.x, tid = threadIdx.x;
    int w = tid >> 5, lane = tid & 31;
    int cg = lane & 7, bg = lane >> 3;  // 8 col-groups x 4 batch-groups
    int gp = cta >> 5, ci = cta & 31;

    // one-time: stage W slice
    {
        const float4* wsrc = (const float4*)(g_whP + (size_t)ci * H_ * LC);
        float4* wdst = (float4*)whsB;
        for (int i = tid; i < H_ * LC / 4; i += 256) wdst[i] = wsrc[i];
    }

    // reduce/gate roles: thread = (j in 16 h-cols, b2 in 16 batches)
    int j = tid >> 4, b2 = tid & 15;
    int hcol = ci * 16 + j;
    float c_state = 0.f;

    // preload cont-weights+bias for this thread's 4 gate cols
    float4 cw[4];
    #pragma unroll
    for (int g = 0; g < 4; ++g) cw[g] = g_cwb[g * H_ + hcol];

    uint32_t hsm_s = (uint32_t)__cvta_generic_to_shared(hsmB);
    float* hbuf0 = g_hbufG + (size_t)gp * 2 * H_ * GB;
    unsigned* bar = g_barG + gp * 32;

    // ---- prologue: stage slot 0 + compute xg(t=0) ----
    if (w == 0) {
        if (lane < 16) {
            int b = gp * GB + lane;
            int bi = boss_anim[b * T_ + 0]; bi = min(max(bi, 0), 49);
            ibuf[(0 * 16 + lane) * 2 + 0] = bi;
            size_t cb = (size_t)b * T_ * 3;
            cbuf[(0 * 16 + lane) * 4 + 0] = cont[cb + 0];
            cbuf[(0 * 16 + lane) * 4 + 1] = cont[cb + 1];
            cbuf[(0 * 16 + lane) * 4 + 2] = cont[cb + 2];
        } else {
            int bb = lane - 16;
            int b = gp * GB + bb;
            int hi = hero_anim[b * T_ + 0]; hi = min(max(hi, 0), 199);
            ibuf[(0 * 16 + bb) * 2 + 1] = hi;
        }
    }
    __syncthreads();

    float xcur[4];
    {
        int bi = ibuf[(0 * 16 + b2) * 2 + 0];
        int hi = ibuf[(0 * 16 + b2) * 2 + 1];
        float c0 = cbuf[(0 * 16 + b2) * 4 + 0];
        float c1 = cbuf[(0 * 16 + b2) * 4 + 1];
        float c2 = cbuf[(0 * 16 + b2) * 4 + 2];
        float4 bv4 = *(const float4*)(g_bossT4 + ((size_t)bi * H_ + hcol) * 4);
        float4 hv4 = *(const float4*)(g_heroT4 + ((size_t)hi * H_ + hcol) * 4);
        xcur[0] = bv4.x + hv4.x + c0 * cw[0].x + c1 * cw[0].y + c2 * cw[0].z + cw[0].w;
        xcur[1] = bv4.y + hv4.y + c0 * cw[1].x + c1 * cw[1].y + c2 * cw[1].z + cw[1].w;
        xcur[2] = bv4.z + hv4.z + c0 * cw[2].x + c1 * cw[2].y + c2 * cw[2].z + cw[2].w;
        xcur[3] = bv4.w + hv4.w + c0 * cw[3].x + c1 * cw[3].y + c2 * cw[3].z + cw[3].w;
    }

    for (int t = 0; t < T_; ++t) {
        int tp = min(t + 1, T_ - 1);
        int nb = (t + 1) & 1;

        // -------- warp0: issue stage loads for t+1 (into regs) --------
        int sbi = 0, shi = 0; float sc0 = 0, sc1 = 0, sc2 = 0;
        if (w == 0) {
            if (lane < 16) {
                int b = gp * GB + lane;
                sbi = boss_anim[b * T_ + tp];
                size_t cb = ((size_t)b * T_ + tp) * 3;
                sc0 = cont[cb + 0]; sc1 = cont[cb + 1]; sc2 = cont[cb + 2];
            } else {
                int b = gp * GB + (lane - 16);
                shi = hero_anim[b * T_ + tp];
            }
        }

        // -------- async-load own 4KB k-slice --------
        const char* src = (const char*)(hbuf0 + (size_t)(t & 1) * H_ * GB) + w * 4096;
        uint32_t dst = hsm_s + w * 4096;
        #pragma unroll
        for (int i = 0; i < 4; ++i) cp16(dst + i * 512 + lane * 16, src + i * 512 + lane * 16);
        cpcommit();
        #pragma unroll
        for (int i = 4; i < 8; ++i) cp16(dst + i * 512 + lane * 16, src + i * 512 + lane * 16);
        cpcommit();

        ull acc[16];
        #pragma unroll
        for (int a = 0; a < 16; ++a) acc[a] = 0ull;

        const char* wP = whsB + (w * 64) * 256 + cg * 16;
        const char* hP = hsmB + (w * 64) * 64 + bg * 16;

        #define GBODY                                                          \
        {                                                                      \
            float4 hv = *(const float4*)(hP);                                  \
            ulonglong2 wA = *(const ulonglong2*)(wP);                          \
            ulonglong2 wB = *(const ulonglong2*)(wP + 128);                    \
            ull h0 = pk2(hv.x, hv.x), h1 = pk2(hv.y, hv.y);                    \
            ull h2 = pk2(hv.z, hv.z), h3 = pk2(hv.w, hv.w);                    \
            fma2(acc[0],  wA.x, h0); fma2(acc[1],  wA.x, h1);                  \
            fma2(acc[2],  wA.x, h2); fma2(acc[3],  wA.x, h3);                  \
            fma2(acc[4],  wA.y, h0); fma2(acc[5],  wA.y, h1);                  \
            fma2(acc[6],  wA.y, h2); fma2(acc[7],  wA.y, h3);                  \
            fma2(acc[8],  wB.x, h0); fma2(acc[9],  wB.x, h1);                  \
            fma2(acc[10], wB.x, h2); fma2(acc[11], wB.x, h3);                  \
            fma2(acc[12], wB.y, h0); fma2(acc[13], wB.y, h1);                  \
            fma2(acc[14], wB.y, h2); fma2(acc[15], wB.y, h3);                  \
            wP += 256; hP += 64;                                               \
        }

        cpwait<1>();
        __syncwarp();
        #pragma unroll 8
        for (int k = 0; k < 32; ++k) GBODY
        cpwait<0>();
        __syncwarp();
        #pragma unroll 8
        for (int k = 0; k < 32; ++k) GBODY
        #undef GBODY

        // -------- warp0: commit stage to smem (before the block sync) --------
        if (w == 0) {
            if (lane < 16) {
                int bi = min(max(sbi, 0), 49);
                ibuf[(nb * 16 + lane) * 2 + 0] = bi;
                cbuf[(nb * 16 + lane) * 4 + 0] = sc0;
                cbuf[(nb * 16 + lane) * 4 + 1] = sc1;
                cbuf[(nb * 16 + lane) * 4 + 2] = sc2;
            } else {
                int hi = min(max(shi, 0), 199);
                ibuf[(nb * 16 + (lane - 16)) * 2 + 1] = hi;
            }
        }

        // -------- store partials [w][b2 (pad 272B)][lc] --------
        #pragma unroll
        for (int b = 0; b < 4; ++b) {
            char* pb = part + w * PS_ + (bg * 4 + b) * 272 + cg * 16;
            *(ulonglong2*)(pb)       = make_ulonglong2(acc[0 + b], acc[4 + b]);
            *(ulonglong2*)(pb + 128) = make_ulonglong2(acc[8 + b], acc[12 + b]);
        }
        __syncthreads();

        // -------- issue gather LDGs for xg(t+1) --------
        int nbi = ibuf[(nb * 16 + b2) * 2 + 0];
        int nhi = ibuf[(nb * 16 + b2) * 2 + 1];
        float nc0 = cbuf[(nb * 16 + b2) * 4 + 0];
        float nc1 = cbuf[(nb * 16 + b2) * 4 + 1];
        float nc2 = cbuf[(nb * 16 + b2) * 4 + 2];
        float4 bv4 = *(const float4*)(g_bossT4 + ((size_t)nbi * H_ + hcol) * 4);
        float4 hv4 = *(const float4*)(g_heroT4 + ((size_t)nhi * H_ + hcol) * 4);

        // -------- fused ksplit reduction + gates (uses xcur) --------
        float gs[4];
        #pragma unroll
        for (int g0 = 0; g0 < 4; ++g0) {
            int lc = g0 * 16 + j;
            float s = 0.f;
            #pragma unroll
            for (int w8 = 0; w8 < 8; ++w8)
                s += *(const float*)(part + w8 * PS_ + b2 * 272 + lc * 4);
            gs[g0] = s;
        }
        float gi = gs[0] + xcur[0], gf = gs[1] + xcur[1];
        float gg = gs[2] + xcur[2], go = gs[3] + xcur[3];
        float iv = sigf(gi), fv = sigf(gf), gv = tanha(gg), ov = sigf(go);
        c_state = fv * c_state + iv * gv;
        float h = ov * tanha(c_state);
        hbuf0[(size_t)nb * H_ * GB + hcol * GB + b2] = h;
        g_hs[((size_t)t * H_ + hcol) * B_ + gp * GB + b2] = h;

        // -------- compute xg(t+1) --------
        xcur[0] = bv4.x + hv4.x + nc0 * cw[0].x + nc1 * cw[0].y + nc2 * cw[0].z + cw[0].w;
        xcur[1] = bv4.y + hv4.y + nc0 * cw[1].x + nc1 * cw[1].y + nc2 * cw[1].z + cw[1].w;
        xcur[2] = bv4.z + hv4.z + nc0 * cw[2].x + nc1 * cw[2].y + nc2 * cw[2].z + cw[2].w;
        xcur[3] = bv4.w + hv4.w + nc0 * cw[3].x + nc1 * cw[3].y + nc2 * cw[3].z + cw[3].w;

        // -------- group barrier (R7-proven form, verbatim) --------
        __threadfence();
        __syncthreads();
        if (tid == 0) {
            atomicAdd(bar, 1u);
            unsigned tgt = (unsigned)GCTA * (unsigned)(t + 1);
            while (*(volatile unsigned*)bar < tgt) { }
            __threadfence();
        }
        __syncthreads();
    }
}

// ---------------- kernel 4: MLP epilogue ----------------
__global__ void __launch_bounds__(256, 1) k_mlp(const float* __restrict__ W1,
                                                const float* __restrict__ b1,
                                                const float* __restrict__ W2,
                                                const float* __restrict__ b2,
                                                float* __restrict__ out) {
    extern __shared__ char smem[];
    float* hsm = (float*)smem;                          // [512][64] 128KB
    float* w1c = (float*)(smem + 131072);               // [64][256] 64KB
    float* b1s = (float*)(smem + 131072 + 65536);       // 256
    float* w2s = b1s + 256;                             // 256
    float* red = w2s + 256;                             // [16][64]

    int t = blockIdx.x, tid = threadIdx.x;

    const float4* hsrc = (const float4*)(g_hs + (size_t)t * (H_ * B_));
    float4* hd = (float4*)hsm;
    for (int i = tid; i < H_ * B_ / 4; i += 256) hd[i] = hsrc[i];
    b1s[tid] = b1[tid];
    w2s[tid] = W2[tid];
    __syncthreads();

    int bt = tid & 15, mt = tid >> 4;
    int b0 = bt * 4, m0 = mt * 16;

    ull acc[16][2];
    #pragma unroll
    for (int m = 0; m < 16; ++m) {
        float bv = b1s[m0 + m];
        acc[m][0] = pk2(bv, bv);
        acc[m][1] = pk2(bv, bv);
    }

    for (int kc = 0; kc < 8; ++kc) {
        if (kc > 0) __syncthreads();
        const float4* wsrc = (const float4*)(W1 + (size_t)kc * 64 * 256);
        for (int i = tid; i < 4096; i += 256) ((float4*)w1c)[i] = wsrc[i];
        __syncthreads();
        #pragma unroll 4
        for (int k = 0; k < 64; ++k) {
            const ull* hp = (const ull*)&hsm[(kc * 64 + k) * B_ + b0];
            ull h01 = hp[0], h23 = hp[1];
            const float* wr = &w1c[k * 256 + m0];
            #pragma unroll
            for (int m4 = 0; m4 < 4; ++m4) {
                float4 wv = *(const float4*)&wr[m4 * 4];
                ull wa = pk2(wv.x, wv.x), wb = pk2(wv.y, wv.y);
                ull wc = pk2(wv.z, wv.z), wd = pk2(wv.w, wv.w);
                fma2(acc[m4 * 4 + 0][0], h01, wa); fma2(acc[m4 * 4 + 0][1], h23, wa);
                fma2(acc[m4 * 4 + 1][0], h01, wb); fma2(acc[m4 * 4 + 1][1], h23, wb);
                fma2(acc[m4 * 4 + 2][0], h01, wc); fma2(acc[m4 * 4 + 2][1], h23, wc);
                fma2(acc[m4 * 4 + 3][0], h01, wd); fma2(acc[m4 * 4 + 3][1], h23, wd);
            }
        }
    }

    float p0 = 0.f, p1 = 0.f, p2 = 0.f, p3 = 0.f;
    #pragma unroll
    for (int m = 0; m < 16; ++m) {
        float2 v0 = upk(acc[m][0]), v1 = upk(acc[m][1]);
        float wv = w2s[m0 + m];
        p0 += fmaxf(v0.x, 0.f) * wv;
        p1 += fmaxf(v0.y, 0.f) * wv;
        p2 += fmaxf(v1.x, 0.f) * wv;
        p3 += fmaxf(v1.y, 0.f) * wv;
    }
    red[mt * B_ + b0 + 0] = p0;
    red[mt * B_ + b0 + 1] = p1;
    red[mt * B_ + b0 + 2] = p2;
    red[mt * B_ + b0 + 3] = p3;
    __syncthreads();
    if (tid < B_) {
        float s = b2[0];
        #pragma unroll
        for (int q = 0; q < 16; ++q) s += red[q * B_ + tid];
        out[(size_t)tid * T_ + t] = s;
    }
}

// ---------------- launch ----------------
extern "C" void kernel_launch(void* const* d_in, const int* in_sizes, int n_in,
                              void* d_out, int out_size) {
    const int*   boss_anim  = (const int*)d_in[0];
    const int*   hero_anim  = (const int*)d_in[1];
    const float* continuous = (const float*)d_in[2];
    const float* boss_table = (const float*)d_in[3];
    const float* hero_table = (const float*)d_in[4];
    const float* W_i        = (const float*)d_in[5];
    const float* W_h        = (const float*)d_in[6];
    const float* b_lstm     = (const float*)d_in[7];
    const float* W1         = (const float*)d_in[8];
    const float* b1         = (const float*)d_in[9];
    const float* W2         = (const float*)d_in[10];
    const float* b2         = (const float*)d_in[11];
    float* out = (float*)d_out;

    static bool attr_done = false;
    if (!attr_done) {
        cudaFuncSetAttribute(k_recur, cudaFuncAttributeMaxDynamicSharedMemorySize, SMTOT);
        cudaFuncSetAttribute(k_mlp,   cudaFuncAttributeMaxDynamicSharedMemorySize, 131072 + 65536 + 2048 + 4096);
        attr_done = true;
    }

    k_init<<<32, 256>>>();
    k_prep<<<G_, 256>>>(boss_table, hero_table, W_i, b_lstm);
    k_prepW<<<512, 256>>>(W_h);
    k_recur<<<NCTA, 256, SMTOT>>>(boss_anim, hero_anim, continuous);
    k_mlp<<<T_, 256, 131072 + 65536 + 2048 + 4096>>>(W1, b1, W2, b2, out);
}

// round 11
// speedup vs baseline: 2.6617x; 1.0167x over previous
#include <cuda_runtime.h>
#include <cuda_bf16.h>
#include <cstdint>

typedef unsigned long long ull;

#define B_    64
#define T_    2048
#define H_    512
#define G_    2048      // 4*H
#define NCTA  128       // 4 groups x 32 CTAs
#define GCTA  32        // CTAs per group
#define GB    16        // batches per group
#define LC    64        // gate cols per CTA

// ---------------- device scratch (static, allowed) ----------------
__device__ __align__(16) float  g_hs[(size_t)T_ * H_ * B_];        // 256 MB [t][k][b] natural
__device__ __align__(16) float  g_whP[GCTA * H_ * LC];             // 4 MB [ci][k][lc]
__device__ __align__(16) float  g_bossT4[50 * H_ * 4];             // [v][hcol][gate]
__device__ __align__(16) float  g_heroT4[200 * H_ * 4];            // [v][hcol][gate]
__device__ __align__(16) float4 g_cwb[G_];                         // (Wc0,Wc1,Wc2,bias) by o
__device__ __align__(16) float  g_hbufG[4 * 2 * H_ * GB];          // per-group double-buffered h
__device__ unsigned g_barG[4 * 32];                                // per-group counters, 128B apart

// ---------------- helpers ----------------
__device__ __forceinline__ ull pk2(float x, float y) {
    ull r; asm("mov.b64 %0, {%1,%2};" : "=l"(r) : "f"(x), "f"(y)); return r;
}
__device__ __forceinline__ float2 upk(ull v) {
    float2 f; asm("mov.b64 {%0,%1}, %2;" : "=f"(f.x), "=f"(f.y) : "l"(v)); return f;
}
__device__ __forceinline__ void fma2(ull& d, ull a, ull b) {
    asm("fma.rn.f32x2 %0, %1, %2, %3;" : "=l"(d) : "l"(a), "l"(b), "l"(d));
}
__device__ __forceinline__ void cp16(uint32_t s, const void* g) {
    asm volatile("cp.async.cg.shared.global [%0], [%1], 16;" :: "r"(s), "l"(g) : "memory");
}
__device__ __forceinline__ void cpcommit() { asm volatile("cp.async.commit_group;" ::: "memory"); }
template <int N> __device__ __forceinline__ void cpwait() {
    asm volatile("cp.async.wait_group %0;" :: "n"(N) : "memory");
}
__device__ __forceinline__ float sigf(float x) { return 1.0f / (1.0f + __expf(-x)); }
__device__ __forceinline__ float tanha(float x) {
    float r; asm("tanh.approx.f32 %0, %1;" : "=f"(r) : "f"(x)); return r;
}

// ---------------- kernel 0: init ----------------
__global__ void k_init() {
    int tid = threadIdx.x + blockIdx.x * blockDim.x;
    if (tid < 4 * 32) g_barG[tid] = 0u;
    for (int i = tid; i < 4 * 2 * H_ * GB; i += blockDim.x * gridDim.x)
        g_hbufG[i] = 0.f;
}

// ---------------- kernel 1: projections (gate-packed tables) ----------------
__global__ void k_prep(const float* __restrict__ boss_table,
                       const float* __restrict__ hero_table,
                       const float* __restrict__ W_i,
                       const float* __restrict__ b_lstm) {
    int o = blockIdx.x;
    int gate = o >> 9, hcol = o & 511;
    int tid = threadIdx.x;
    if (tid < 50) {
        float s = 0.f;
        #pragma unroll
        for (int e = 0; e < 32; ++e) s += boss_table[tid * 32 + e] * W_i[e * G_ + o];
        g_bossT4[(tid * H_ + hcol) * 4 + gate] = s;
    } else if (tid < 250) {
        int v = tid - 50;
        float s = 0.f;
        #pragma unroll
        for (int e = 0; e < 32; ++e) s += hero_table[v * 32 + e] * W_i[(32 + e) * G_ + o];
        g_heroT4[(v * H_ + hcol) * 4 + gate] = s;
    } else if (tid == 250) {
        g_cwb[o] = make_float4(W_i[64 * G_ + o], W_i[65 * G_ + o], W_i[66 * G_ + o], b_lstm[o]);
    }
}

// ---------------- kernel 1b: W_h permute -> whP[ci][k][lc] ----------------
__global__ void k_prepW(const float* __restrict__ W_h) {
    int ci = blockIdx.x >> 4, kb = blockIdx.x & 15;
    int tid = threadIdx.x;
    int k = kb * 32 + (tid >> 3);
    int lc0 = (tid & 7) * 8;
    #pragma unroll
    for (int l = 0; l < 8; ++l) {
        int lc = lc0 + l;
        int gate = lc >> 4, j = lc & 15;
        int o = gate * H_ + ci * 16 + j;
        g_whP[((size_t)ci * H_ + k) * LC + lc] = W_h[(size_t)k * G_ + o];
    }
}

// ---------------- kernel 3: persistent LSTM recurrence ----------------
#define SM_W    0
#define SM_H    131072
#define SM_P    (131072 + 32768)
#define PS_     4352            // partial stride per warp: 16 rows x 272B
#define SM_STG  (SM_P + 8 * PS_)
#define SMTOT   (SM_STG + 1024)
__global__ void __launch_bounds__(256, 1) k_recur(const int* __restrict__ boss_anim,
                                                  const int* __restrict__ hero_anim,
                                                  const float* __restrict__ cont) {
    extern __shared__ char smem[];
    char* whsB = smem + SM_W;           // [512][256B]
    char* hsmB = smem + SM_H;           // [512][64B]
    char* part = smem + SM_P;           // [8][16][272B]
    int*   ibuf = (int*)(smem + SM_STG);           // [2][16][2]
    float* cbuf = (float*)(smem + SM_STG + 256);   // [2][16][4]

    int cta = blockIdx.x, tid = threadIdx.x;
    int w = tid >> 5, lane = tid & 31;
    int cg = lane & 7, bg = lane >> 3;  // 8 col-groups x 4 batch-groups
    int gp = cta >> 5, ci = cta & 31;

    // one-time: stage W slice
    {
        const float4* wsrc = (const float4*)(g_whP + (size_t)ci * H_ * LC);
        float4* wdst = (float4*)whsB;
        for (int i = tid; i < H_ * LC / 4; i += 256) wdst[i] = wsrc[i];
    }

    // reduce/gate roles: thread = (j in 16 h-cols, b2 in 16 batches)
    int j = tid >> 4, b2 = tid & 15;
    int hcol = ci * 16 + j;
    float c_state = 0.f;

    // preload cont-weights+bias for this thread's 4 gate cols
    float4 cw[4];
    #pragma unroll
    for (int g = 0; g < 4; ++g) cw[g] = g_cwb[g * H_ + hcol];

    uint32_t hsm_s = (uint32_t)__cvta_generic_to_shared(hsmB);
    float* hbuf0 = g_hbufG + (size_t)gp * 2 * H_ * GB;
    unsigned* bar = g_barG + gp * 32;

    // ---- prologue: stage slot 0 + compute xg(t=0) ----
    if (w == 0) {
        if (lane < 16) {
            int b = gp * GB + lane;
            int bi = boss_anim[b * T_ + 0]; bi = min(max(bi, 0), 49);
            ibuf[(0 * 16 + lane) * 2 + 0] = bi;
            size_t cb = (size_t)b * T_ * 3;
            cbuf[(0 * 16 + lane) * 4 + 0] = cont[cb + 0];
            cbuf[(0 * 16 + lane) * 4 + 1] = cont[cb + 1];
            cbuf[(0 * 16 + lane) * 4 + 2] = cont[cb + 2];
        } else {
            int bb = lane - 16;
            int b = gp * GB + bb;
            int hi = hero_anim[b * T_ + 0]; hi = min(max(hi, 0), 199);
            ibuf[(0 * 16 + bb) * 2 + 1] = hi;
        }
    }
    __syncthreads();

    float xcur[4];
    {
        int bi = ibuf[(0 * 16 + b2) * 2 + 0];
        int hi = ibuf[(0 * 16 + b2) * 2 + 1];
        float c0 = cbuf[(0 * 16 + b2) * 4 + 0];
        float c1 = cbuf[(0 * 16 + b2) * 4 + 1];
        float c2 = cbuf[(0 * 16 + b2) * 4 + 2];
        float4 bv4 = *(const float4*)(g_bossT4 + ((size_t)bi * H_ + hcol) * 4);
        float4 hv4 = *(const float4*)(g_heroT4 + ((size_t)hi * H_ + hcol) * 4);
        xcur[0] = bv4.x + hv4.x + c0 * cw[0].x + c1 * cw[0].y + c2 * cw[0].z + cw[0].w;
        xcur[1] = bv4.y + hv4.y + c0 * cw[1].x + c1 * cw[1].y + c2 * cw[1].z + cw[1].w;
        xcur[2] = bv4.z + hv4.z + c0 * cw[2].x + c1 * cw[2].y + c2 * cw[2].z + cw[2].w;
        xcur[3] = bv4.w + hv4.w + c0 * cw[3].x + c1 * cw[3].y + c2 * cw[3].z + cw[3].w;
    }

    for (int t = 0; t < T_; ++t) {
        int tp = min(t + 1, T_ - 1);
        int nb = (t + 1) & 1;

        // -------- async-load own 4KB k-slice FIRST (4 groups of 2 cp16) --------
        const char* src = (const char*)(hbuf0 + (size_t)(t & 1) * H_ * GB) + w * 4096;
        uint32_t dst = hsm_s + w * 4096;
        #pragma unroll
        for (int g = 0; g < 4; ++g) {
            cp16(dst + (g * 2 + 0) * 512 + lane * 16, src + (g * 2 + 0) * 512 + lane * 16);
            cp16(dst + (g * 2 + 1) * 512 + lane * 16, src + (g * 2 + 1) * 512 + lane * 16);
            cpcommit();
        }

        // -------- warp0: issue stage loads for t+1 (into regs) --------
        int sbi = 0, shi = 0; float sc0 = 0, sc1 = 0, sc2 = 0;
        if (w == 0) {
            if (lane < 16) {
                int b = gp * GB + lane;
                sbi = boss_anim[b * T_ + tp];
                size_t cb = ((size_t)b * T_ + tp) * 3;
                sc0 = cont[cb + 0]; sc1 = cont[cb + 1]; sc2 = cont[cb + 2];
            } else {
                int b = gp * GB + (lane - 16);
                shi = hero_anim[b * T_ + tp];
            }
        }

        ull acc[16];
        #pragma unroll
        for (int a = 0; a < 16; ++a) acc[a] = 0ull;

        const char* wP = whsB + (w * 64) * 256 + cg * 16;
        const char* hP = hsmB + (w * 64) * 64 + bg * 16;

        #define GBODY                                                          \
        {                                                                      \
            float4 hv = *(const float4*)(hP);                                  \
            ulonglong2 wA = *(const ulonglong2*)(wP);                          \
            ulonglong2 wB = *(const ulonglong2*)(wP + 128);                    \
            ull h0 = pk2(hv.x, hv.x), h1 = pk2(hv.y, hv.y);                    \
            ull h2 = pk2(hv.z, hv.z), h3 = pk2(hv.w, hv.w);                    \
            fma2(acc[0],  wA.x, h0); fma2(acc[1],  wA.x, h1);                  \
            fma2(acc[2],  wA.x, h2); fma2(acc[3],  wA.x, h3);                  \
            fma2(acc[4],  wA.y, h0); fma2(acc[5],  wA.y, h1);                  \
            fma2(acc[6],  wA.y, h2); fma2(acc[7],  wA.y, h3);                  \
            fma2(acc[8],  wB.x, h0); fma2(acc[9],  wB.x, h1);                  \
            fma2(acc[10], wB.x, h2); fma2(acc[11], wB.x, h3);                  \
            fma2(acc[12], wB.y, h0); fma2(acc[13], wB.y, h1);                  \
            fma2(acc[14], wB.y, h2); fma2(acc[15], wB.y, h3);                  \
            wP += 256; hP += 64;                                               \
        }

        // -------- GEMM: 4 chunks of 16 k, each gated by its cp group --------
        cpwait<3>();
        __syncwarp();
        #pragma unroll 8
        for (int k = 0; k < 16; ++k) GBODY
        cpwait<2>();
        __syncwarp();
        #pragma unroll 8
        for (int k = 0; k < 16; ++k) GBODY
        cpwait<1>();
        __syncwarp();
        #pragma unroll 8
        for (int k = 0; k < 16; ++k) GBODY
        cpwait<0>();
        __syncwarp();
        #pragma unroll 8
        for (int k = 0; k < 16; ++k) GBODY
        #undef GBODY

        // -------- warp0: commit stage to smem (before the block sync) --------
        if (w == 0) {
            if (lane < 16) {
                int bi = min(max(sbi, 0), 49);
                ibuf[(nb * 16 + lane) * 2 + 0] = bi;
                cbuf[(nb * 16 + lane) * 4 + 0] = sc0;
                cbuf[(nb * 16 + lane) * 4 + 1] = sc1;
                cbuf[(nb * 16 + lane) * 4 + 2] = sc2;
            } else {
                int hi = min(max(shi, 0), 199);
                ibuf[(nb * 16 + (lane - 16)) * 2 + 1] = hi;
            }
        }

        // -------- store partials [w][b2 (pad 272B)][lc] --------
        #pragma unroll
        for (int b = 0; b < 4; ++b) {
            char* pb = part + w * PS_ + (bg * 4 + b) * 272 + cg * 16;
            *(ulonglong2*)(pb)       = make_ulonglong2(acc[0 + b], acc[4 + b]);
            *(ulonglong2*)(pb + 128) = make_ulonglong2(acc[8 + b], acc[12 + b]);
        }
        __syncthreads();

        // -------- issue gather LDGs for xg(t+1) --------
        int nbi = ibuf[(nb * 16 + b2) * 2 + 0];
        int nhi = ibuf[(nb * 16 + b2) * 2 + 1];
        float nc0 = cbuf[(nb * 16 + b2) * 4 + 0];
        float nc1 = cbuf[(nb * 16 + b2) * 4 + 1];
        float nc2 = cbuf[(nb * 16 + b2) * 4 + 2];
        float4 bv4 = *(const float4*)(g_bossT4 + ((size_t)nbi * H_ + hcol) * 4);
        float4 hv4 = *(const float4*)(g_heroT4 + ((size_t)nhi * H_ + hcol) * 4);

        // -------- fused ksplit reduction + gates (uses xcur) --------
        float gs[4];
        #pragma unroll
        for (int g0 = 0; g0 < 4; ++g0) {
            int lc = g0 * 16 + j;
            float s = 0.f;
            #pragma unroll
            for (int w8 = 0; w8 < 8; ++w8)
                s += *(const float*)(part + w8 * PS_ + b2 * 272 + lc * 4);
            gs[g0] = s;
        }
        float gi = gs[0] + xcur[0], gf = gs[1] + xcur[1];
        float gg = gs[2] + xcur[2], go = gs[3] + xcur[3];
        float iv = sigf(gi), fv = sigf(gf), gv = tanha(gg), ov = sigf(go);
        c_state = fv * c_state + iv * gv;
        float h = ov * tanha(c_state);
        hbuf0[(size_t)nb * H_ * GB + hcol * GB + b2] = h;

        // -------- compute xg(t+1) --------
        xcur[0] = bv4.x + hv4.x + nc0 * cw[0].x + nc1 * cw[0].y + nc2 * cw[0].z + cw[0].w;
        xcur[1] = bv4.y + hv4.y + nc0 * cw[1].x + nc1 * cw[1].y + nc2 * cw[1].z + cw[1].w;
        xcur[2] = bv4.z + hv4.z + nc0 * cw[2].x + nc1 * cw[2].y + nc2 * cw[2].z + cw[2].w;
        xcur[3] = bv4.w + hv4.w + nc0 * cw[3].x + nc1 * cw[3].y + nc2 * cw[3].z + cw[3].w;

        // -------- group barrier (R7/R9-proven form) with archive store
        //          overlapped into the spin window --------
        __threadfence();
        __syncthreads();
        g_hs[((size_t)t * H_ + hcol) * B_ + gp * GB + b2] = h;   // off the drain path
        if (tid == 0) {
            atomicAdd(bar, 1u);
            unsigned tgt = (unsigned)GCTA * (unsigned)(t + 1);
            while (*(volatile unsigned*)bar < tgt) { }
            __threadfence();
        }
        __syncthreads();
    }
}

// ---------------- kernel 4: MLP epilogue ----------------
__global__ void __launch_bounds__(256, 1) k_mlp(const float* __restrict__ W1,
                                                const float* __restrict__ b1,
                                                const float* __restrict__ W2,
                                                const float* __restrict__ b2,
                                                float* __restrict__ out) {
    extern __shared__ char smem[];
    float* hsm = (float*)smem;                          // [512][64] 128KB
    float* w1c = (float*)(smem + 131072);               // [64][256] 64KB
    float* b1s = (float*)(smem + 131072 + 65536);       // 256
    float* w2s = b1s + 256;                             // 256
    float* red = w2s + 256;                             // [16][64]

    int t = blockIdx.x, tid = threadIdx.x;

    const float4* hsrc = (const float4*)(g_hs + (size_t)t * (H_ * B_));
    float4* hd = (float4*)hsm;
    for (int i = tid; i < H_ * B_ / 4; i += 256) hd[i] = hsrc[i];
    b1s[tid] = b1[tid];
    w2s[tid] = W2[tid];
    __syncthreads();

    int bt = tid & 15, mt = tid >> 4;
    int b0 = bt * 4, m0 = mt * 16;

    ull acc[16][2];
    #pragma unroll
    for (int m = 0; m < 16; ++m) {
        float bv = b1s[m0 + m];
        acc[m][0] = pk2(bv, bv);
        acc[m][1] = pk2(bv, bv);
    }

    for (int kc = 0; kc < 8; ++kc) {
        if (kc > 0) __syncthreads();
        const float4* wsrc = (const float4*)(W1 + (size_t)kc * 64 * 256);
        for (int i = tid; i < 4096; i += 256) ((float4*)w1c)[i] = wsrc[i];
        __syncthreads();
        #pragma unroll 4
        for (int k = 0; k < 64; ++k) {
            const ull* hp = (const ull*)&hsm[(kc * 64 + k) * B_ + b0];
            ull h01 = hp[0], h23 = hp[1];
            const float* wr = &w1c[k * 256 + m0];
            #pragma unroll
            for (int m4 = 0; m4 < 4; ++m4) {
                float4 wv = *(const float4*)&wr[m4 * 4];
                ull wa = pk2(wv.x, wv.x), wb = pk2(wv.y, wv.y);
                ull wc = pk2(wv.z, wv.z), wd = pk2(wv.w, wv.w);
                fma2(acc[m4 * 4 + 0][0], h01, wa); fma2(acc[m4 * 4 + 0][1], h23, wa);
                fma2(acc[m4 * 4 + 1][0], h01, wb); fma2(acc[m4 * 4 + 1][1], h23, wb);
                fma2(acc[m4 * 4 + 2][0], h01, wc); fma2(acc[m4 * 4 + 2][1], h23, wc);
                fma2(acc[m4 * 4 + 3][0], h01, wd); fma2(acc[m4 * 4 + 3][1], h23, wd);
            }
        }
    }

    float p0 = 0.f, p1 = 0.f, p2 = 0.f, p3 = 0.f;
    #pragma unroll
    for (int m = 0; m < 16; ++m) {
        float2 v0 = upk(acc[m][0]), v1 = upk(acc[m][1]);
        float wv = w2s[m0 + m];
        p0 += fmaxf(v0.x, 0.f) * wv;
        p1 += fmaxf(v0.y, 0.f) * wv;
        p2 += fmaxf(v1.x, 0.f) * wv;
        p3 += fmaxf(v1.y, 0.f) * wv;
    }
    red[mt * B_ + b0 + 0] = p0;
    red[mt * B_ + b0 + 1] = p1;
    red[mt * B_ + b0 + 2] = p2;
    red[mt * B_ + b0 + 3] = p3;
    __syncthreads();
    if (tid < B_) {
        float s = b2[0];
        #pragma unroll
        for (int q = 0; q < 16; ++q) s += red[q * B_ + tid];
        out[(size_t)tid * T_ + t] = s;
    }
}

// ---------------- launch ----------------
extern "C" void kernel_launch(void* const* d_in, const int* in_sizes, int n_in,
                              void* d_out, int out_size) {
    const int*   boss_anim  = (const int*)d_in[0];
    const int*   hero_anim  = (const int*)d_in[1];
    const float* continuous = (const float*)d_in[2];
    const float* boss_table = (const float*)d_in[3];
    const float* hero_table = (const float*)d_in[4];
    const float* W_i        = (const float*)d_in[5];
    const float* W_h        = (const float*)d_in[6];
    const float* b_lstm     = (const float*)d_in[7];
    const float* W1         = (const float*)d_in[8];
    const float* b1         = (const float*)d_in[9];
    const float* W2         = (const float*)d_in[10];
    const float* b2         = (const float*)d_in[11];
    float* out = (float*)d_out;

    static bool attr_done = false;
    if (!attr_done) {
        cudaFuncSetAttribute(k_recur, cudaFuncAttributeMaxDynamicSharedMemorySize, SMTOT);
        cudaFuncSetAttribute(k_mlp,   cudaFuncAttributeMaxDynamicSharedMemorySize, 131072 + 65536 + 2048 + 4096);
        attr_done = true;
    }

    k_init<<<32, 256>>>();
    k_prep<<<G_, 256>>>(boss_table, hero_table, W_i, b_lstm);
    k_prepW<<<512, 256>>>(W_h);
    k_recur<<<NCTA, 256, SMTOT>>>(boss_anim, hero_anim, continuous);
    k_mlp<<<T_, 256, 131072 + 65536 + 2048 + 4096>>>(W1, b1, W2, b2, out);
}